// round 3
// baseline (speedup 1.0000x reference)
// Flash attention (B=4, S=4096, D=128, fp32) via tf32 mma.sync, FA2-style.
// - 128 CTAs (32 Q-tiles x 4 batches), 256 threads (8 warps), 1 wave on 148 SMs
// - BLOCK_M=128 (16 rows/warp), BLOCK_N=64, online softmax in fp32
// - Q/K/V/P rounded to tf32 (cvt.rna) once per element in smem
// - K/V double-buffered with cp.async.cg; per-operand smem padding for
//   conflict-free mma fragment loads (K stride 132, V stride 136, P stride 68)
#include <cuda_runtime.h>
#include <math.h>
#include <stdint.h>

#define BM 128
#define BN 64
#define HD 128
#define KST 132   // K smem row stride (floats): conflict-free for QK B-frags
#define VST 136   // V smem row stride: conflict-free for PV B-frags
#define PST 68    // P smem row stride
#define NTHREADS 256
#define ATTN_SCALE 0.08838834764831845f  // 1/sqrt(128)

__device__ __forceinline__ float tf32r(float x) {
    unsigned u;
    asm("cvt.rna.tf32.f32 %0, %1;" : "=r"(u) : "f"(x));
    return __uint_as_float(u);
}

__device__ __forceinline__ void cp_async16(float* dst, const float* src) {
    unsigned s = (unsigned)__cvta_generic_to_shared(dst);
    asm volatile("cp.async.cg.shared.global [%0], [%1], 16;" :: "r"(s), "l"(src));
}

__device__ __forceinline__ void mma_tf32(float c[4], const unsigned a[4],
                                         unsigned b0, unsigned b1) {
    asm volatile(
        "mma.sync.aligned.m16n8k8.row.col.f32.tf32.tf32.f32 "
        "{%0,%1,%2,%3}, {%4,%5,%6,%7}, {%8,%9}, {%0,%1,%2,%3};"
        : "+f"(c[0]), "+f"(c[1]), "+f"(c[2]), "+f"(c[3])
        : "r"(a[0]), "r"(a[1]), "r"(a[2]), "r"(a[3]), "r"(b0), "r"(b1));
}

__global__ void __launch_bounds__(NTHREADS, 1)
fattn_tf32_kernel(const float* __restrict__ q, const float* __restrict__ k,
                  const float* __restrict__ v, float* __restrict__ out, int S)
{
    extern __shared__ float sm[];
    float* sKb = sm;                     // 2 * BN*KST floats
    float* sVb = sm + 2 * BN * KST;      // 2 * BN*VST floats
    float* sPb = sVb + 2 * BN * VST;     // 8 warps * 16*PST floats

    const int tid  = threadIdx.x;
    const int warp = tid >> 5;
    const int lane = tid & 31;
    const int g = lane >> 2;             // groupID (row within 8)
    const int t = lane & 3;              // threadID_in_group

    const int b  = blockIdx.y;
    const int m0 = blockIdx.x * BM;

    const float* qb = q + ((long)b * S + m0) * HD;
    const float* kb = k + (long)b * S * HD;
    const float* vb = v + (long)b * S * HD;
    float* ob = out + ((long)b * S + m0) * HD;
    float* sPw = sPb + warp * 16 * PST;

    // ---- Stage Q (tf32-rounded) into the sV area, extract A-fragments ----
    float* sQ = sVb;  // 2*BN*VST = 17408 floats >= 128*KST = 16896 needed
    #pragma unroll
    for (int j = 0; j < 16; j++) {
        int idx = tid + j * NTHREADS;          // 0..4095 float4s
        int r = idx >> 5, c = (idx & 31) << 2;
        float4 x = *(const float4*)(qb + r * HD + c);
        x.x = tf32r(x.x); x.y = tf32r(x.y); x.z = tf32r(x.z); x.w = tf32r(x.w);
        *(float4*)(sQ + r * KST + c) = x;
    }
    __syncthreads();

    // A-frag (m16n8k8 tf32): a0=(g,kt) a1=(g+8,kt) a2=(g,kt+4) a3=(g+8,kt+4)
    unsigned qf[16][4];
    {
        const float* qr = sQ + (warp * 16 + g) * KST;
        #pragma unroll
        for (int kk = 0; kk < 16; kk++) {
            qf[kk][0] = __float_as_uint(qr[kk*8 + t]);
            qf[kk][1] = __float_as_uint(qr[8*KST + kk*8 + t]);
            qf[kk][2] = __float_as_uint(qr[kk*8 + t + 4]);
            qf[kk][3] = __float_as_uint(qr[8*KST + kk*8 + t + 4]);
        }
    }
    __syncthreads();

    float o[16][4];
    #pragma unroll
    for (int d = 0; d < 16; d++) { o[d][0]=0.f; o[d][1]=0.f; o[d][2]=0.f; o[d][3]=0.f; }
    float mr0 = -INFINITY, mr1 = -INFINITY, l0 = 0.f, l1 = 0.f;

    const int NT = S / BN;

    // ---- Issue tile 0 ----
    {
        #pragma unroll
        for (int j = 0; j < 8; j++) {
            int idx = tid + j*NTHREADS; int r = idx >> 5, c = (idx & 31) << 2;
            cp_async16(sKb + r*KST + c, kb + r*HD + c);
        }
        #pragma unroll
        for (int j = 0; j < 8; j++) {
            int idx = tid + j*NTHREADS; int r = idx >> 5, c = (idx & 31) << 2;
            cp_async16(sVb + r*VST + c, vb + r*HD + c);
        }
        asm volatile("cp.async.commit_group;" ::: "memory");
    }

    for (int nt = 0; nt < NT; nt++) {
        const int buf = nt & 1;
        float* Kb = sKb + buf * (BN*KST);
        float* Vb = sVb + buf * (BN*VST);

        asm volatile("cp.async.wait_group 0;" ::: "memory");
        __syncthreads();

        // Round current tile to tf32 in place (once per element)
        #pragma unroll
        for (int j = 0; j < 8; j++) {
            int idx = tid + j*NTHREADS; int r = idx >> 5, c = (idx & 31) << 2;
            float4* pk = (float4*)(Kb + r*KST + c);
            float4 x = *pk;
            x.x = tf32r(x.x); x.y = tf32r(x.y); x.z = tf32r(x.z); x.w = tf32r(x.w);
            *pk = x;
            float4* pv = (float4*)(Vb + r*VST + c);
            float4 y = *pv;
            y.x = tf32r(y.x); y.y = tf32r(y.y); y.z = tf32r(y.z); y.w = tf32r(y.w);
            *pv = y;
        }
        __syncthreads();

        // Prefetch next tile into the other buffer (overlaps with compute)
        if (nt + 1 < NT) {
            float* dK = sKb + (buf^1) * (BN*KST);
            float* dV = sVb + (buf^1) * (BN*VST);
            const float* kg = kb + (long)(nt+1) * BN * HD;
            const float* vg = vb + (long)(nt+1) * BN * HD;
            #pragma unroll
            for (int j = 0; j < 8; j++) {
                int idx = tid + j*NTHREADS; int r = idx >> 5, c = (idx & 31) << 2;
                cp_async16(dK + r*KST + c, kg + r*HD + c);
            }
            #pragma unroll
            for (int j = 0; j < 8; j++) {
                int idx = tid + j*NTHREADS; int r = idx >> 5, c = (idx & 31) << 2;
                cp_async16(dV + r*VST + c, vg + r*HD + c);
            }
            asm volatile("cp.async.commit_group;" ::: "memory");
        }

        // ---- S = Q K^T (raw, scale folded into exp) ----
        float s[8][4];
        #pragma unroll
        for (int n = 0; n < 8; n++) { s[n][0]=0.f; s[n][1]=0.f; s[n][2]=0.f; s[n][3]=0.f; }
        #pragma unroll
        for (int n = 0; n < 8; n++) {
            const float* kp = Kb + (n*8 + g) * KST;  // B-frag: b0=K[n8+g][k8+t]
            #pragma unroll
            for (int kk = 0; kk < 16; kk++) {
                unsigned b0 = __float_as_uint(kp[kk*8 + t]);
                unsigned b1 = __float_as_uint(kp[kk*8 + t + 4]);
                mma_tf32(s[n], qf[kk], b0, b1);
            }
        }

        // ---- online softmax (rows g and g+8, reduce within lane quad) ----
        float mx0 = -INFINITY, mx1 = -INFINITY;
        #pragma unroll
        for (int n = 0; n < 8; n++) {
            mx0 = fmaxf(mx0, fmaxf(s[n][0], s[n][1]));
            mx1 = fmaxf(mx1, fmaxf(s[n][2], s[n][3]));
        }
        mx0 = fmaxf(mx0, __shfl_xor_sync(0xffffffffu, mx0, 1));
        mx0 = fmaxf(mx0, __shfl_xor_sync(0xffffffffu, mx0, 2));
        mx1 = fmaxf(mx1, __shfl_xor_sync(0xffffffffu, mx1, 1));
        mx1 = fmaxf(mx1, __shfl_xor_sync(0xffffffffu, mx1, 2));
        float mn0 = fmaxf(mr0, mx0), mn1 = fmaxf(mr1, mx1);
        float a0 = __expf((mr0 - mn0) * ATTN_SCALE);
        float a1 = __expf((mr1 - mn1) * ATTN_SCALE);
        mr0 = mn0; mr1 = mn1;

        float sum0 = 0.f, sum1 = 0.f;
        #pragma unroll
        for (int n = 0; n < 8; n++) {
            float p0 = __expf((s[n][0] - mn0) * ATTN_SCALE);
            float p1 = __expf((s[n][1] - mn0) * ATTN_SCALE);
            float p2 = __expf((s[n][2] - mn1) * ATTN_SCALE);
            float p3 = __expf((s[n][3] - mn1) * ATTN_SCALE);
            sum0 += p0 + p1; sum1 += p2 + p3;
            // C-frag (g, 8n+2t / +1) -> smem, tf32-rounded
            *(float2*)(sPw + g*PST + n*8 + 2*t)     = make_float2(tf32r(p0), tf32r(p1));
            *(float2*)(sPw + (g+8)*PST + n*8 + 2*t) = make_float2(tf32r(p2), tf32r(p3));
        }
        sum0 += __shfl_xor_sync(0xffffffffu, sum0, 1);
        sum0 += __shfl_xor_sync(0xffffffffu, sum0, 2);
        sum1 += __shfl_xor_sync(0xffffffffu, sum1, 1);
        sum1 += __shfl_xor_sync(0xffffffffu, sum1, 2);
        l0 = l0 * a0 + sum0;
        l1 = l1 * a1 + sum1;
        #pragma unroll
        for (int d = 0; d < 16; d++) {
            o[d][0] *= a0; o[d][1] *= a0; o[d][2] *= a1; o[d][3] *= a1;
        }
        __syncwarp();   // sPw written above is read below by other lanes

        // P as A-fragments
        unsigned pa[8][4];
        #pragma unroll
        for (int kk = 0; kk < 8; kk++) {
            pa[kk][0] = __float_as_uint(sPw[g*PST + kk*8 + t]);
            pa[kk][1] = __float_as_uint(sPw[(g+8)*PST + kk*8 + t]);
            pa[kk][2] = __float_as_uint(sPw[g*PST + kk*8 + t + 4]);
            pa[kk][3] = __float_as_uint(sPw[(g+8)*PST + kk*8 + t + 4]);
        }

        // ---- O += P V  (B-frag: b0=V[k8+t][d8+g], b1=V[k8+t+4][d8+g]) ----
        const float* vt = Vb + t * VST + g;
        #pragma unroll
        for (int d = 0; d < 16; d++) {
            #pragma unroll
            for (int kk = 0; kk < 8; kk++) {
                unsigned b0 = __float_as_uint(vt[(kk*8)     * VST + d*8]);
                unsigned b1 = __float_as_uint(vt[(kk*8 + 4) * VST + d*8]);
                mma_tf32(o[d], pa[kk], b0, b1);
            }
        }
        // (next-iteration top __syncthreads orders sPw/K/V reuse)
    }

    // ---- epilogue: O /= l, write out ----
    float inv0 = 1.f / l0, inv1 = 1.f / l1;
    float* or0 = ob + (warp*16 + g) * HD;
    float* or1 = or0 + 8 * HD;
    #pragma unroll
    for (int d = 0; d < 16; d++) {
        *(float2*)(or0 + d*8 + 2*t) = make_float2(o[d][0]*inv0, o[d][1]*inv0);
        *(float2*)(or1 + d*8 + 2*t) = make_float2(o[d][2]*inv1, o[d][3]*inv1);
    }
}

extern "C" void kernel_launch(void* const* d_in, const int* in_sizes, int n_in,
                              void* d_out, int out_size) {
    const float* q = (const float*)d_in[0];
    const float* k = (const float*)d_in[1];
    const float* v = (const float*)d_in[2];
    float* out = (float*)d_out;

    const int S = 4096, D = 128;
    const int B = in_sizes[0] / (S * D);

    const size_t smem = (size_t)(2*BN*KST + 2*BN*VST + 8*16*PST) * sizeof(float); // 172,032 B
    cudaFuncSetAttribute(fattn_tf32_kernel,
                         cudaFuncAttributeMaxDynamicSharedMemorySize, (int)smem);

    dim3 grid(S / BM, B);
    fattn_tf32_kernel<<<grid, NTHREADS, smem>>>(q, k, v, out, S);
}